// round 13
// baseline (speedup 1.0000x reference)
#include <cuda_runtime.h>
#include <cuda_fp16.h>
#include <cstdint>
#include <cstddef>

#define EPS   1e-6f
#define B_    16
#define NN    1024
#define FDIM  64
#define OUTD  128
#define KC    32
#define NITER (NN / KC)

// strides in b32 units
#define SA_STRH 20      // stage rows: 64 B data + 16 B pad
#define OC_STRH 100
#define KM_STRH 100

// smem layout (bytes)
#define OFF_ADIAG 0
#define OFF_INV   512
#define OFF_SROW  1024
#define OFF_DYN   1536
#define ASTG_B    (128 * SA_STRH * 4)              // 10240
#define STG_B     (2 * ASTG_B)                     // 20480 (A + B)
#define OFF_STAGE(s) (OFF_DYN + (s) * STG_B)
#define OFF_OC    OFF_DYN                          // 51200 B (inside stages 0-2)
#define OFF_KM    (OFF_DYN + 4 * STG_B)            // 83456
#define SMEM_BYTES (OFF_KM + 128 * KM_STRH * 4)    // 134656

__device__ float  g_inv[B_ * NN];
__device__ float  g_s[B_ * NN];
__device__ __half g_Ah[(size_t)B_ * NN * NN];    // fp16 copy of A (diag kept)
__device__ __half g_Bh[(size_t)B_ * 128 * NN];   // [b][f:128][k] fp16; f>=64 = s*x

__device__ __forceinline__ uint32_t smem_u32(const void* p) {
    uint32_t a;
    asm("{ .reg .u64 t; cvta.to.shared.u64 t, %1; cvt.u32.u64 %0, t; }"
        : "=r"(a) : "l"(p));
    return a;
}
__device__ __forceinline__ void cp_async16(uint32_t saddr, const void* g) {
    asm volatile("cp.async.cg.shared.global [%0], [%1], 16;"
                 :: "r"(saddr), "l"(g) : "memory");
}
#define CP_COMMIT() asm volatile("cp.async.commit_group;" ::: "memory")
#define CP_WAIT2()  asm volatile("cp.async.wait_group 2;" ::: "memory")
__device__ __forceinline__ uint32_t h2pack(float lo, float hi) {
    __half2 h = __floats2half2_rn(lo, hi);
    return *(uint32_t*)&h;
}
__device__ __forceinline__ float h2f_rn(float v) {
    return __half2float(__float2half_rn(v));
}
__device__ __forceinline__ void mma_f16(float* c, const uint32_t* a, const uint32_t* b) {
    asm volatile(
        "mma.sync.aligned.m16n8k16.row.col.f32.f16.f16.f32 "
        "{%0,%1,%2,%3}, {%4,%5,%6,%7}, {%8,%9}, {%0,%1,%2,%3};"
        : "+f"(c[0]), "+f"(c[1]), "+f"(c[2]), "+f"(c[3])
        : "r"(a[0]), "r"(a[1]), "r"(a[2]), "r"(a[3]), "r"(b[0]), "r"(b[1]));
}

// ---------------------------------------------------------------------------
// Kernel 1: deg + fp16-A conversion. One warp per (b,i) row; the row is
// already in registers for the sum, so the fp16 write is nearly free.
// ---------------------------------------------------------------------------
__global__ void deg_prep_kernel(const float* __restrict__ A) {
    int warp = (blockIdx.x * blockDim.x + threadIdx.x) >> 5;
    int lane = threadIdx.x & 31;
    if (warp >= B_ * NN) return;
    const float* row = A + (size_t)warp * NN;
    const float4* r4 = (const float4*)row;
    float4 v[8];
    float sum = 0.f;
#pragma unroll
    for (int w = 0; w < 8; w++) {
        v[w] = r4[w * 32 + lane];
        sum += v[w].x + v[w].y + v[w].z + v[w].w;
    }
#pragma unroll
    for (int off = 16; off > 0; off >>= 1)
        sum += __shfl_down_sync(0xFFFFFFFFu, sum, off);
    if (lane == 0) {
        float deg = sum - row[warp % NN] + 1.0f;
        g_inv[warp] = 1.0f / (EPS + deg);
        g_s[warp]   = 1.0f / (EPS + sqrtf(deg));
    }
    uint2* dst = (uint2*)(g_Ah + (size_t)warp * NN);
#pragma unroll
    for (int w = 0; w < 8; w++) {
        uint2 h;
        h.x = h2pack(v[w].x, v[w].y);
        h.y = h2pack(v[w].z, v[w].w);
        dst[w * 32 + lane] = h;
    }
}

// ---------------------------------------------------------------------------
// Kernel 2: transpose+convert x -> g_Bh[b][f][k] fp16 (f>=64 holds s*x)
// ---------------------------------------------------------------------------
__global__ __launch_bounds__(256, 4)
void prep_kernel(const float* __restrict__ x) {
    __shared__ float xt[128][65];
    __shared__ float sk[128];
    const int b = blockIdx.y, k0 = blockIdx.x * 128;
    const int tid = threadIdx.x;
    const float* xb = x + ((size_t)b * NN + k0) * FDIM;
#pragma unroll
    for (int q = 0; q < 8; q++) {
        int e = tid + q * 256;
        int row = e >> 4, c4 = (e & 15) * 4;
        float4 v = *(const float4*)&xb[(size_t)row * FDIM + c4];
        xt[row][c4] = v.x; xt[row][c4 + 1] = v.y;
        xt[row][c4 + 2] = v.z; xt[row][c4 + 3] = v.w;
    }
    if (tid < 128) sk[tid] = g_s[b * NN + k0 + tid];
    __syncthreads();
    uint32_t* dst = (uint32_t*)(g_Bh + (size_t)b * 128 * NN + k0);
#pragma unroll
    for (int q = 0; q < 32; q++) {
        int e = tid + q * 256;
        int f = e >> 6, kp = e & 63;
        float v0, v1;
        if (f < 64) {
            v0 = xt[2 * kp][f];
            v1 = xt[2 * kp + 1][f];
        } else {
            v0 = sk[2 * kp] * xt[2 * kp][f - 64];
            v1 = sk[2 * kp + 1] * xt[2 * kp + 1][f - 64];
        }
        dst[(size_t)f * (NN / 2) + kp] = h2pack(v0, v1);
    }
}

// ---------------------------------------------------------------------------
// Kernel 3: fused fp16 GEMMs. 512 threads, ALL warps compute (32x32 tiles).
// Classic 4-stage cp.async multistage pipeline (wait_group 2, empty-commit
// tail). Mainloop has zero LDG / cvt / STS.
// ---------------------------------------------------------------------------
__global__ __launch_bounds__(512, 1)
void fused_mma_kernel(const float* __restrict__ A, const float* __restrict__ x,
                      const float* __restrict__ Kmat, const float* __restrict__ bias,
                      float* __restrict__ out) {
    extern __shared__ char smc[];
    float* smf = (float*)smc;
    const uint32_t sb = smem_u32(smc);
    const int tid  = threadIdx.x;
    const int wid  = tid >> 5;
    const int lane = tid & 31;
    const int b    = blockIdx.y;
    const int row0 = blockIdx.x * 128;
    const int lr = lane >> 2;
    const int lc = lane & 3;

    const float* Ab = A + (size_t)b * NN * NN;
    const float* xb = x + (size_t)b * NN * FDIM;

    // warp tile: rows mm..mm+31, cols n4..n4+31 (same mapping for GEMM1/2)
    const int mm = (wid >> 2) * 32;
    const int n4 = (wid & 3) * 32;
    const bool scaled = (n4 >= 64);
    const int f_base = scaled ? n4 - 64 : n4;

    // ---- cp.async geometry: per stage, 1 A-chunk + 1 B-chunk per thread
    const int srow = tid >> 2;               // 0..127
    const int sch  = (tid & 3) * 8;          // half offset within 64B row
    const __half* gA = g_Ah + (size_t)b * NN * NN + (size_t)(row0 + srow) * NN + sch;
    const __half* gB = g_Bh + (size_t)b * 128 * NN + (size_t)srow * NN + sch;
    uint32_t sAaddr[4], sBaddr[4];
#pragma unroll
    for (int s = 0; s < 4; s++) {
        sAaddr[s] = sb + OFF_STAGE(s) + srow * 80 + (tid & 3) * 16;
        sBaddr[s] = sAaddr[s] + ASTG_B;
    }

    // ---- prologue: issue stages 0..2
#pragma unroll
    for (int st = 0; st < 3; st++) {
        cp_async16(sAaddr[st], gA + st * KC);
        cp_async16(sBaddr[st], gB + st * KC);
        CP_COMMIT();
    }

    // ---- stage scalars + KmatT fp16 (overlaps in-flight cp.async)
    if (tid < 128) {
        int grow = row0 + tid;
        smf[(OFF_ADIAG >> 2) + tid] = h2f_rn(__ldg(&Ab[(size_t)grow * NN + grow]));
        smf[(OFF_INV >> 2) + tid]   = g_inv[b * NN + grow];
        smf[(OFF_SROW >> 2) + tid]  = g_s[b * NN + grow];
    }
    {
        uint32_t* km = (uint32_t*)(smc + OFF_KM);
#pragma unroll 1
        for (int e = tid; e < 128 * 96; e += 512) {
            int n = e / 96;
            int kp = e - n * 96;
            float v0 = __ldg(&Kmat[(size_t)(2 * kp) * 128 + n]);
            float v1 = __ldg(&Kmat[(size_t)(2 * kp + 1) * 128 + n]);
            km[n * KM_STRH + kp] = h2pack(v0, v1);
        }
    }

    float acc[2][4][4];
#pragma unroll
    for (int mt = 0; mt < 2; mt++)
#pragma unroll
        for (int nt = 0; nt < 4; nt++)
#pragma unroll
            for (int q = 0; q < 4; q++) acc[mt][nt][q] = 0.f;

    // ---- mainloop: 32 iters; exactly one commit per iter keeps the FIFO
    // count uniform so wait_group 2 always means "stage it is ready".
    for (int it = 0; it < NITER; ++it) {
        CP_WAIT2();
        __syncthreads();
        if (it + 3 < NITER) {
            const int st = (it + 3) & 3;
            cp_async16(sAaddr[st], gA + (it + 3) * KC);
            cp_async16(sBaddr[st], gB + (it + 3) * KC);
        }
        CP_COMMIT();   // possibly-empty group: keeps group count uniform
        const uint32_t* sA = (const uint32_t*)(smc + OFF_STAGE(it & 3));
        const uint32_t* sB = sA + (ASTG_B >> 2);
#pragma unroll
        for (int ks = 0; ks < 2; ks++) {
            const int kb = ks * 8;
            uint32_t af[2][4], bf2[4][2];
#pragma unroll
            for (int mt = 0; mt < 2; mt++) {
                const uint32_t* p = sA + (mm + mt * 16 + lr) * SA_STRH + kb + lc;
                af[mt][0] = p[0];
                af[mt][1] = p[8 * SA_STRH];
                af[mt][2] = p[4];
                af[mt][3] = p[8 * SA_STRH + 4];
            }
#pragma unroll
            for (int nt = 0; nt < 4; nt++) {
                const uint32_t* p = sB + (n4 + nt * 8 + lr) * SA_STRH + kb + lc;
                bf2[nt][0] = p[0];
                bf2[nt][1] = p[4];
            }
#pragma unroll
            for (int mt = 0; mt < 2; mt++)
#pragma unroll
                for (int nt = 0; nt < 4; nt++)
                    mma_f16(acc[mt][nt], af[mt], bf2[nt]);
        }
    }
    __syncthreads();   // all reads of stage bufs done before OC overwrite

    // ---- epilogue 1: analytic diagonal fix -> ocat fp16 [128][192]
    {
        uint32_t* oc = (uint32_t*)(smc + OFF_OC);
#pragma unroll
        for (int mt = 0; mt < 2; mt++) {
#pragma unroll
            for (int nt = 0; nt < 4; nt++) {
                const int f = f_base + nt * 8 + lc * 2;
#pragma unroll
                for (int h = 0; h < 2; h++) {
                    const int r = mm + mt * 16 + lr + h * 8;
                    const float ad = smf[(OFF_ADIAG >> 2) + r];
                    const float c0 = acc[mt][nt][h * 2 + 0];
                    const float c1 = acc[mt][nt][h * 2 + 1];
                    float2 xv = *(const float2*)&xb[(size_t)(row0 + r) * FDIM + f];
                    if (!scaled) {
                        const float inv = smf[(OFF_INV >> 2) + r];
                        float xhx = h2f_rn(xv.x), xhy = h2f_rn(xv.y);
                        float o1a = c0 - ad * xhx;
                        float o1b = c1 - ad * xhy;
                        oc[r * OC_STRH + (f >> 1)] = h2pack(o1a, o1b);
                        oc[r * OC_STRH + ((64 + f) >> 1)] =
                            h2pack(inv * (o1a + xv.x), inv * (o1b + xv.y));
                    } else {
                        const float sv = smf[(OFF_SROW >> 2) + r];
                        float sxx = h2f_rn(sv * xv.x), sxy = h2f_rn(sv * xv.y);
                        float o3a = sv * c0 - sv * ad * sxx + sv * sv * xv.x;
                        float o3b = sv * c1 - sv * ad * sxy + sv * sv * xv.y;
                        oc[r * OC_STRH + ((128 + f) >> 1)] = h2pack(o3a, o3b);
                    }
                }
            }
        }
    }
    __syncthreads();

    // ---- GEMM2: out[128,128] = ocat[128,192] @ KmatT^T  (fp16, 12 k-steps)
    const uint32_t* ocp = (const uint32_t*)(smc + OFF_OC);
    const uint32_t* kmp = (const uint32_t*)(smc + OFF_KM);
    float acc2[2][4][4];
#pragma unroll
    for (int mt = 0; mt < 2; mt++)
#pragma unroll
        for (int nt = 0; nt < 4; nt++)
#pragma unroll
            for (int q = 0; q < 4; q++) acc2[mt][nt][q] = 0.f;

#pragma unroll
    for (int ks = 0; ks < 12; ks++) {
        const int kb = ks * 8;
        uint32_t af[2][4], bf2[4][2];
#pragma unroll
        for (int mt = 0; mt < 2; mt++) {
            const uint32_t* p = ocp + (mm + mt * 16 + lr) * OC_STRH + kb + lc;
            af[mt][0] = p[0];
            af[mt][1] = p[8 * OC_STRH];
            af[mt][2] = p[4];
            af[mt][3] = p[8 * OC_STRH + 4];
        }
#pragma unroll
        for (int nt = 0; nt < 4; nt++) {
            const uint32_t* p = kmp + (n4 + nt * 8 + lr) * KM_STRH + kb + lc;
            bf2[nt][0] = p[0];
            bf2[nt][1] = p[4];
        }
#pragma unroll
        for (int mt = 0; mt < 2; mt++)
#pragma unroll
            for (int nt = 0; nt < 4; nt++)
                mma_f16(acc2[mt][nt], af[mt], bf2[nt]);
    }

    // ---- bias + relu + store
#pragma unroll
    for (int mt = 0; mt < 2; mt++) {
#pragma unroll
        for (int nt = 0; nt < 4; nt++) {
            const int col = n4 + nt * 8 + lc * 2;
            float2 bv = *(const float2*)&bias[col];
#pragma unroll
            for (int h = 0; h < 2; h++) {
                const int r = mm + mt * 16 + lr + h * 8;
                float2 o;
                o.x = fmaxf(acc2[mt][nt][h * 2 + 0] + bv.x, 0.f);
                o.y = fmaxf(acc2[mt][nt][h * 2 + 1] + bv.y, 0.f);
                *(float2*)&out[((size_t)b * NN + row0 + r) * OUTD + col] = o;
            }
        }
    }
}

// ---------------------------------------------------------------------------
extern "C" void kernel_launch(void* const* d_in, const int* in_sizes, int n_in,
                              void* d_out, int out_size) {
    const float *x = nullptr, *A = nullptr, *Kmat = nullptr, *bias = nullptr;
    for (int i = 0; i < n_in; i++) {
        switch (in_sizes[i]) {
            case B_ * NN * FDIM:  x    = (const float*)d_in[i]; break;
            case B_ * NN * NN:    A    = (const float*)d_in[i]; break;
            case 3 * FDIM * OUTD: Kmat = (const float*)d_in[i]; break;
            case OUTD:            bias = (const float*)d_in[i]; break;
        }
    }
    float* out = (float*)d_out;

    static bool attr_set = false;
    if (!attr_set) {
        cudaFuncSetAttribute(fused_mma_kernel,
                             cudaFuncAttributeMaxDynamicSharedMemorySize, SMEM_BYTES);
        attr_set = true;
    }

    deg_prep_kernel<<<(B_ * NN * 32 + 255) / 256, 256>>>(A);
    prep_kernel<<<dim3(NN / 128, B_), 256>>>(x);
    fused_mma_kernel<<<dim3(NN / 128, B_), 512, SMEM_BYTES>>>(A, x, Kmat, bias, out);
}